// round 17
// baseline (speedup 1.0000x reference)
#include <cuda_runtime.h>
#include <cuda_bf16.h>
#include <math.h>
#include <stdint.h>

#define NB 32
#define NINP 256
#define NHW 1024
#define NCS 64
#define NAOUT 256
#define NCF 513
#define NC5 256
#define EPSV 1e-5f
#define KP 544
#define NCHUNK 17

// ---------------- scratch ------------------------------------------------------
__device__ float g_theta[NB * NCS * NHW];   // [b][c][p] fp32
__device__ float g_phi[NB * NCS * NHW];     // [b][c][p] fp32
__device__ __align__(16) __nv_bfloat16 g_wch[192 * NINP];       // stacked folded conv w
__device__ __align__(16) __nv_bfloat16 g_wcl[192 * NINP];
__device__ __align__(16) __nv_bfloat16 g_w4h[NAOUT * NHW];      // w4 split [o][j]
__device__ __align__(16) __nv_bfloat16 g_w4l[NAOUT * NHW];
__device__ __align__(16) __nv_bfloat16 g_pTh[NB * NCS * NHW];   // P^T split [b][c][j]
__device__ __align__(16) __nv_bfloat16 g_pTl[NB * NCS * NHW];
__device__ __align__(16) __nv_bfloat16 g_thh[NB * NCS * NHW];   // theta split [b][c][p]
__device__ __align__(16) __nv_bfloat16 g_thl[NB * NCS * NHW];
__device__ float g_WPp[4][NB * 512 * NCS];  // fp32 K-split partials
__device__ __align__(16) __nv_bfloat16 g_WPh[NB * 512 * NCS];   // [b][row][c]
__device__ __align__(16) __nv_bfloat16 g_WPl[NB * 512 * NCS];
__device__ __align__(16) __nv_bfloat16 g_yh[NB * NHW * KP];     // [b][p][f'] hi
__device__ __align__(16) __nv_bfloat16 g_yl[NB * NHW * KP];
__device__ float g_part[2][NB * NHW];       // partial logits per M-half
__device__ __align__(16) __nv_bfloat16 g_w5h[NC5 * KP];
__device__ __align__(16) __nv_bfloat16 g_w5l[NC5 * KP];
__device__ float g_sc[3 * NCS];
__device__ float g_sh[3 * NCS];
__device__ float g_sh5[NC5];

__device__ __forceinline__ float f4get(const float4& v, int i) {
    return i == 0 ? v.x : (i == 1 ? v.y : (i == 2 ? v.z : v.w));
}

__device__ __forceinline__ uint32_t smem_u32(const void* p) {
    uint32_t a;
    asm("{ .reg .u64 t; cvta.to.shared.u64 t, %1; cvt.u32.u64 %0, t; }" : "=r"(a) : "l"(p));
    return a;
}

__device__ __forceinline__ void bf16_split(float v, __nv_bfloat16& h, __nv_bfloat16& l) {
    h = __float2bfloat16_rn(v);
    l = __float2bfloat16_rn(v - __bfloat162float(h));
}

__device__ __forceinline__ uint32_t pk2(__nv_bfloat16 a, __nv_bfloat16 b) {
    __nv_bfloat162 t; t.x = a; t.y = b;
    return *reinterpret_cast<uint32_t*>(&t);
}

__device__ __forceinline__ void ldsm4(uint32_t& r0, uint32_t& r1, uint32_t& r2, uint32_t& r3,
                                      uint32_t addr) {
    asm volatile("ldmatrix.sync.aligned.m8n8.x4.shared.b16 {%0,%1,%2,%3}, [%4];"
                 : "=r"(r0), "=r"(r1), "=r"(r2), "=r"(r3) : "r"(addr));
}

#define MMA_BF16(ACC, A0, A1, A2, A3, B0, B1)                                        \
    asm volatile(                                                                    \
        "mma.sync.aligned.m16n8k16.row.col.f32.bf16.bf16.f32 "                       \
        "{%0,%1,%2,%3}, {%4,%5,%6,%7}, {%8,%9}, {%0,%1,%2,%3};"                      \
        : "+f"((ACC)[0]), "+f"((ACC)[1]), "+f"((ACC)[2]), "+f"((ACC)[3])             \
        : "r"(A0), "r"(A1), "r"(A2), "r"(A3), "r"(B0), "r"(B1))

// ---------------- K0: params, w5/convw/w4 split, y pad zero -------------------
__global__ void k0_prep(const float* __restrict__ w5,
                        const float* __restrict__ g5, const float* __restrict__ v5,
                        const float* __restrict__ b5, const float* __restrict__ bt5,
                        const float* __restrict__ m5, const float* __restrict__ w4,
                        const float* __restrict__ w1, const float* __restrict__ b1,
                        const float* __restrict__ g1, const float* __restrict__ bt1,
                        const float* __restrict__ m1, const float* __restrict__ v1,
                        const float* __restrict__ w2, const float* __restrict__ b2,
                        const float* __restrict__ g2, const float* __restrict__ bt2,
                        const float* __restrict__ m2, const float* __restrict__ v2,
                        const float* __restrict__ w3, const float* __restrict__ b3,
                        const float* __restrict__ g3, const float* __restrict__ bt3,
                        const float* __restrict__ m3, const float* __restrict__ v3)
{
    const int blk = blockIdx.x;
    const int tid = threadIdx.x;
    if (blk < NC5) {
        const int k = blk;
        float s5 = g5[k] * rsqrtf(v5[k] + EPSV);
        for (int f = tid; f < KP; f += 256) {
            float val;
            if (f < 512) val = w5[k * NCF + 1 + f] * s5;
            else if (f == 512) val = w5[k * NCF] * s5;
            else val = 0.f;
            __nv_bfloat16 h, l;
            bf16_split(val, h, l);
            g_w5h[k * KP + f] = h;
            g_w5l[k * KP + f] = l;
        }
    } else if (blk == NC5) {
        const int k = tid;
        float s5 = g5[k] * rsqrtf(v5[k] + EPSV);
        g_sh5[k] = (b5[k] - m5[k]) * s5 + bt5[k];
        if (k < 3 * NCS) {
            int cv = k / NCS, c = k % NCS;
            const float* bb = cv == 0 ? b1 : (cv == 1 ? b2 : b3);
            const float* gg = cv == 0 ? g1 : (cv == 1 ? g2 : g3);
            const float* bt = cv == 0 ? bt1 : (cv == 1 ? bt2 : bt3);
            const float* mm = cv == 0 ? m1 : (cv == 1 ? m2 : m3);
            const float* vv = cv == 0 ? v1 : (cv == 1 ? v2 : v3);
            float s = gg[c] * rsqrtf(vv[c] + EPSV);
            g_sc[k] = s;
            g_sh[k] = (bb[c] - mm[c]) * s + bt[c];
        }
    } else if (blk < NC5 + 1 + NB) {
        const int b = blk - NC5 - 1;
        char* baseh = (char*)(g_yh + (size_t)b * NHW * KP + 512);
        char* basel = (char*)(g_yl + (size_t)b * NHW * KP + 512);
        uint4 z = make_uint4(0u, 0u, 0u, 0u);
        for (int i = tid; i < NHW * 4; i += 256) {
            int p = i >> 2, q = i & 3;
            *reinterpret_cast<uint4*>(baseh + (size_t)p * (KP * 2) + q * 16) = z;
            *reinterpret_cast<uint4*>(basel + (size_t)p * (KP * 2) + q * 16) = z;
        }
    } else if (blk < NC5 + 1 + NB + 192) {
        const int row = blk - (NC5 + 1 + NB);
        const int cv = row >> 6, c = row & 63;
        const float* W  = cv == 0 ? w1 : (cv == 1 ? w2 : w3);
        const float* gg = cv == 0 ? g1 : (cv == 1 ? g2 : g3);
        const float* vv = cv == 0 ? v1 : (cv == 1 ? v2 : v3);
        float s = gg[c] * rsqrtf(vv[c] + EPSV);
        float val = W[c * NINP + tid] * s;
        __nv_bfloat16 h, l;
        bf16_split(val, h, l);
        g_wch[row * NINP + tid] = h;
        g_wcl[row * NINP + tid] = l;
    } else {
        const int row = blk - (NC5 + 1 + NB + 192);
        float4 v = *reinterpret_cast<const float4*>(w4 + (size_t)row * NHW + tid * 4);
        __nv_bfloat16 h0, l0, h1, l1, h2, l2, h3, l3;
        bf16_split(v.x, h0, l0); bf16_split(v.y, h1, l1);
        bf16_split(v.z, h2, l2); bf16_split(v.w, h3, l3);
        size_t base = (size_t)row * NHW + tid * 4;
        *reinterpret_cast<uint2*>(&g_w4h[base]) = make_uint2(pk2(h0, h1), pk2(h2, h3));
        *reinterpret_cast<uint2*>(&g_w4l[base]) = make_uint2(pk2(l0, l1), pk2(l2, l3));
    }
}

// ---------------- K1: conv GEMM C[192,128px] = Wc[192,256] @ x^T --------------
__global__ void __launch_bounds__(384) k1_mma(const float* __restrict__ x)
{
    extern __shared__ __nv_bfloat16 smb[];
    const int AH = 0, AL = 15360, BH = 30720, BL = 40960;
    const uint32_t smb_u = smem_u32(smb);
    const int tid = threadIdx.x;
    const int lane = tid & 31;
    const int wid = tid >> 5;
    const int mw3 = wid % 3;
    const int nw4 = wid / 3;
    const int b = blockIdx.y;
    const int p0 = blockIdx.x * 128;
    const float* xb = x + (size_t)b * NINP * NHW;

    const int lrA = lane & 15;
    const int lkA = (lane >> 4) << 3;
    const int lnB = (lane & 7) + ((lane >> 4) << 3);
    const int lkB = ((lane >> 3) & 1) << 3;

    float acc[4][4][4];
#pragma unroll
    for (int mi = 0; mi < 4; mi++)
#pragma unroll
        for (int ni = 0; ni < 4; ni++)
#pragma unroll
            for (int c = 0; c < 4; c++) acc[mi][ni][c] = 0.f;

#define K1_COPYA(ch, buf) do {                                                        \
    for (int i = tid; i < 768; i += 384) {                                            \
        int row = i >> 2, q = i & 3;                                                  \
        uint32_t dh = smb_u + (uint32_t)(AH + (buf) * 7680 + row * 40 + q * 8) * 2u;  \
        uint32_t dl = smb_u + (uint32_t)(AL + (buf) * 7680 + row * 40 + q * 8) * 2u;  \
        size_t so = (size_t)row * NINP + (ch) * 32 + q * 8;                           \
        asm volatile("cp.async.ca.shared.global [%0], [%1], 16;" :: "r"(dh), "l"(g_wch + so)); \
        asm volatile("cp.async.ca.shared.global [%0], [%1], 16;" :: "r"(dl), "l"(g_wcl + so)); \
    }                                                                                 \
    asm volatile("cp.async.commit_group;");                                           \
} while (0)

#define K1_BUILDB(ch, buf) do {                                                       \
    for (int i = tid; i < 512; i += 384) {                                            \
        int cpair = i & 15, pq = i >> 4;                                              \
        const float* src = xb + (size_t)((ch) * 32 + cpair * 2) * NHW + p0 + pq * 4;  \
        float4 v0 = *reinterpret_cast<const float4*>(src);                            \
        float4 v1 = *reinterpret_cast<const float4*>(src + NHW);                      \
        _Pragma("unroll")                                                             \
        for (int j = 0; j < 4; j++) {                                                 \
            __nv_bfloat16 h0, l0, h1, l1;                                             \
            bf16_split(f4get(v0, j), h0, l0);                                         \
            bf16_split(f4get(v1, j), h1, l1);                                         \
            int eo = (pq * 4 + j) * 40 + cpair * 2;                                   \
            *reinterpret_cast<uint32_t*>(smb + BH + (buf) * 5120 + eo) = pk2(h0, h1); \
            *reinterpret_cast<uint32_t*>(smb + BL + (buf) * 5120 + eo) = pk2(l0, l1); \
        }                                                                             \
    }                                                                                 \
} while (0)

    K1_COPYA(0, 0);
    K1_BUILDB(0, 0);
    for (int ch = 0; ch < 8; ch++) {
        if (ch < 7) {
            K1_COPYA(ch + 1, (ch + 1) & 1);
            K1_BUILDB(ch + 1, (ch + 1) & 1);
            asm volatile("cp.async.wait_group 1;");
        } else {
            asm volatile("cp.async.wait_group 0;");
        }
        __syncthreads();
        const int buf = ch & 1;
        const uint32_t AHu = smb_u + (uint32_t)(AH + buf * 7680) * 2u;
        const uint32_t ALu = smb_u + (uint32_t)(AL + buf * 7680) * 2u;
        const uint32_t BHu = smb_u + (uint32_t)(BH + buf * 5120) * 2u;
        const uint32_t BLu = smb_u + (uint32_t)(BL + buf * 5120) * 2u;
#pragma unroll
        for (int ks = 0; ks < 2; ks++) {
            uint32_t ah[4][4], al[4][4], bh[4][2], bl[4][2];
            const uint32_t aoff = (uint32_t)(lrA * 40 + ks * 16 + lkA) * 2u;
            const uint32_t boff = (uint32_t)(lnB * 40 + ks * 16 + lkB) * 2u;
#pragma unroll
            for (int mi = 0; mi < 4; mi++) {
                uint32_t rbase = (uint32_t)((mw3 * 64 + mi * 16) * 40) * 2u;
                ldsm4(ah[mi][0], ah[mi][1], ah[mi][2], ah[mi][3], AHu + rbase + aoff);
                ldsm4(al[mi][0], al[mi][1], al[mi][2], al[mi][3], ALu + rbase + aoff);
            }
#pragma unroll
            for (int no = 0; no < 2; no++) {
                uint32_t nbase = (uint32_t)((nw4 * 32 + no * 16) * 40) * 2u;
                ldsm4(bh[2 * no][0], bh[2 * no][1], bh[2 * no + 1][0], bh[2 * no + 1][1],
                      BHu + nbase + boff);
                ldsm4(bl[2 * no][0], bl[2 * no][1], bl[2 * no + 1][0], bl[2 * no + 1][1],
                      BLu + nbase + boff);
            }
#pragma unroll
            for (int mi = 0; mi < 4; mi++)
#pragma unroll
                for (int ni = 0; ni < 4; ni++) {
                    MMA_BF16(acc[mi][ni], al[mi][0], al[mi][1], al[mi][2], al[mi][3],
                             bh[ni][0], bh[ni][1]);
                    MMA_BF16(acc[mi][ni], ah[mi][0], ah[mi][1], ah[mi][2], ah[mi][3],
                             bl[ni][0], bl[ni][1]);
                    MMA_BF16(acc[mi][ni], ah[mi][0], ah[mi][1], ah[mi][2], ah[mi][3],
                             bh[ni][0], bh[ni][1]);
                }
        }
        __syncthreads();
    }
#undef K1_COPYA
#undef K1_BUILDB

    const int ar = lane >> 2;
    const int qq = lane & 3;
    if (mw3 < 2) {
        float* dst = (mw3 == 0 ? g_theta : g_phi) + (size_t)b * NCS * NHW;
#pragma unroll
        for (int mi = 0; mi < 4; mi++)
#pragma unroll
            for (int rh = 0; rh < 2; rh++) {
                int c = mi * 16 + ar + rh * 8;
                float sh = g_sh[mw3 * 64 + c];
#pragma unroll
                for (int ni = 0; ni < 4; ni++) {
                    int px = p0 + nw4 * 32 + ni * 8 + 2 * qq;
                    float2 o;
                    o.x = fmaxf(acc[mi][ni][rh * 2 + 0] + sh, 0.f);
                    o.y = fmaxf(acc[mi][ni][rh * 2 + 1] + sh, 0.f);
                    *reinterpret_cast<float2*>(dst + (size_t)c * NHW + px) = o;
                    if (mw3 == 0) {
                        __nv_bfloat16 h0, l0, h1, l1;
                        bf16_split(o.x, h0, l0);
                        bf16_split(o.y, h1, l1);
                        size_t tb = (size_t)b * NCS * NHW + (size_t)c * NHW + px;
                        *reinterpret_cast<uint32_t*>(&g_thh[tb]) = pk2(h0, h1);
                        *reinterpret_cast<uint32_t*>(&g_thl[tb]) = pk2(l0, l1);
                    }
                }
            }
    } else {
        float s_px[8];
#pragma unroll
        for (int ni = 0; ni < 4; ni++)
#pragma unroll
            for (int j = 0; j < 2; j++) {
                float s = 0.f;
#pragma unroll
                for (int mi = 0; mi < 4; mi++)
#pragma unroll
                    for (int rh = 0; rh < 2; rh++) {
                        int c = mi * 16 + ar + rh * 8;
                        s += fmaxf(acc[mi][ni][rh * 2 + j] + g_sh[128 + c], 0.f);
                    }
                s_px[ni * 2 + j] = s;
            }
#pragma unroll
        for (int v = 0; v < 8; v++) {
            s_px[v] += __shfl_xor_sync(0xffffffffu, s_px[v], 4);
            s_px[v] += __shfl_xor_sync(0xffffffffu, s_px[v], 8);
            s_px[v] += __shfl_xor_sync(0xffffffffu, s_px[v], 16);
        }
        if (lane < 4) {
#pragma unroll
            for (int ni = 0; ni < 4; ni++)
#pragma unroll
                for (int j = 0; j < 2; j++) {
                    int px = p0 + nw4 * 32 + ni * 8 + 2 * lane + j;
                    float val = s_px[ni * 2 + j] * (1.f / NCS);
                    __nv_bfloat16 h, l;
                    bf16_split(val, h, l);
                    size_t base = (size_t)(b * NHW + px) * KP + 512;
                    g_yh[base] = h;
                    g_yl[base] = l;
                }
        }
    }
}

// ---------------- K2t: transpose+split phi -> P^T -----------------------------
__global__ void __launch_bounds__(256) k2t()
{
    __shared__ float sm[64 * 68];
    const int jt = blockIdx.x;
    const int b = blockIdx.y;
    const int tid = threadIdx.x;

    const float* src = g_phi + (size_t)b * NCS * NHW + jt * 4096;
    for (int i = tid; i < 1024; i += 256) {
        int r = i >> 4, cq = i & 15;
        float4 v = *reinterpret_cast<const float4*>(src + r * 64 + cq * 4);
        *reinterpret_cast<float4*>(sm + r * 68 + cq * 4) = v;
    }
    __syncthreads();
    const int jg = tid >> 6;
    const int c = tid & 63;
    uint32_t hb[8], lb[8];
#pragma unroll
    for (int k2i = 0; k2i < 8; k2i++) {
        __nv_bfloat16 h0, l0, h1, l1;
        bf16_split(sm[(jg * 16 + k2i * 2) * 68 + c], h0, l0);
        bf16_split(sm[(jg * 16 + k2i * 2 + 1) * 68 + c], h1, l1);
        hb[k2i] = pk2(h0, h1);
        lb[k2i] = pk2(l0, l1);
    }
    size_t base = (size_t)b * NCS * NHW + (size_t)c * NHW + jt * 64 + jg * 16;
    *reinterpret_cast<uint4*>(&g_pTh[base])     = make_uint4(hb[0], hb[1], hb[2], hb[3]);
    *reinterpret_cast<uint4*>(&g_pTh[base + 8]) = make_uint4(hb[4], hb[5], hb[6], hb[7]);
    *reinterpret_cast<uint4*>(&g_pTl[base])     = make_uint4(lb[0], lb[1], lb[2], lb[3]);
    *reinterpret_cast<uint4*>(&g_pTl[base + 8]) = make_uint4(lb[4], lb[5], lb[6], lb[7]);
}

// ---------------- K2: K-split mma GEMM -> fp32 partials (32-k stages) ---------
// grid (4 otiles, 2 which, NB*4 ksplit), 128 thr; each CTA: K chunk of 256
// smem: 4 arrays x 2 bufs x (64 rows x 40) = 20480 el = 40960 B -> 5 CTAs/SM
__global__ void __launch_bounds__(128) k2_mma()
{
    extern __shared__ __nv_bfloat16 smb[];
    const int AH = 0, AL = 5120, BH = 10240, BL = 15360;
    const uint32_t smb_u = smem_u32(smb);
    const int tid = threadIdx.x;
    const int lane = tid & 31;
    const int wid = tid >> 5;
    const int mw = wid & 1;
    const int nw = wid >> 1;
    const int o0 = blockIdx.x * 64;
    const int which = blockIdx.y;
    const int ksp = blockIdx.z & 3;
    const int b = blockIdx.z >> 2;

    const int lrA = lane & 15;
    const int lkA = (lane >> 4) << 3;
    const int lnB = (lane & 7) + ((lane >> 4) << 3);
    const int lkB = ((lane >> 3) & 1) << 3;

    const __nv_bfloat16* Asrch = g_w4h + (size_t)o0 * NHW;
    const __nv_bfloat16* Asrcl = g_w4l + (size_t)o0 * NHW;
    const __nv_bfloat16* Bsrch = (which ? g_thh : g_pTh) + (size_t)b * NCS * NHW;
    const __nv_bfloat16* Bsrcl = (which ? g_thl : g_pTl) + (size_t)b * NCS * NHW;

    float acc[2][4][4];
#pragma unroll
    for (int mi = 0; mi < 2; mi++)
#pragma unroll
        for (int ni = 0; ni < 4; ni++)
#pragma unroll
            for (int c = 0; c < 4; c++) acc[mi][ni][c] = 0.f;

// stage: 64 rows x 32 k = 256 x 16B per array (16B = 8 bf16, 4 quads/row)
#define K2_COPY(ch, buf) do {                                                         \
    for (int i = tid; i < 256; i += 128) {                                            \
        int row = i >> 2, q = i & 3;                                                  \
        uint32_t dh = smb_u + (uint32_t)(AH + (buf) * 2560 + row * 40 + q * 8) * 2u;  \
        uint32_t dl = smb_u + (uint32_t)(AL + (buf) * 2560 + row * 40 + q * 8) * 2u;  \
        size_t so = (size_t)row * NHW + (ch) * 32 + q * 8;                            \
        asm volatile("cp.async.ca.shared.global [%0], [%1], 16;" :: "r"(dh), "l"(Asrch + so)); \
        asm volatile("cp.async.ca.shared.global [%0], [%1], 16;" :: "r"(dl), "l"(Asrcl + so)); \
    }                                                                                 \
    for (int i = tid; i < 256; i += 128) {                                            \
        int row = i >> 2, q = i & 3;                                                  \
        uint32_t dh = smb_u + (uint32_t)(BH + (buf) * 2560 + row * 40 + q * 8) * 2u;  \
        uint32_t dl = smb_u + (uint32_t)(BL + (buf) * 2560 + row * 40 + q * 8) * 2u;  \
        size_t so = (size_t)row * NHW + (ch) * 32 + q * 8;                            \
        asm volatile("cp.async.ca.shared.global [%0], [%1], 16;" :: "r"(dh), "l"(Bsrch + so)); \
        asm volatile("cp.async.ca.shared.global [%0], [%1], 16;" :: "r"(dl), "l"(Bsrcl + so)); \
    }                                                                                 \
    asm volatile("cp.async.commit_group;");                                           \
} while (0)

    const int ch0 = ksp * 8;
    K2_COPY(ch0, 0);
    for (int ci = 0; ci < 8; ci++) {
        if (ci < 7) {
            K2_COPY(ch0 + ci + 1, (ci + 1) & 1);
            asm volatile("cp.async.wait_group 1;");
        } else {
            asm volatile("cp.async.wait_group 0;");
        }
        __syncthreads();
        const int buf = ci & 1;
        const uint32_t AHu = smb_u + (uint32_t)(AH + buf * 2560) * 2u;
        const uint32_t ALu = smb_u + (uint32_t)(AL + buf * 2560) * 2u;
        const uint32_t BHu = smb_u + (uint32_t)(BH + buf * 2560) * 2u;
        const uint32_t BLu = smb_u + (uint32_t)(BL + buf * 2560) * 2u;
#pragma unroll
        for (int ks = 0; ks < 2; ks++) {
            uint32_t ah[2][4], al[2][4], bh[4][2], bl[4][2];
            const uint32_t aoff = (uint32_t)(lrA * 40 + ks * 16 + lkA) * 2u;
            const uint32_t boff = (uint32_t)(lnB * 40 + ks * 16 + lkB) * 2u;
#pragma unroll
            for (int mi = 0; mi < 2; mi++) {
                uint32_t rbase = (uint32_t)((mw * 32 + mi * 16) * 40) * 2u;
                ldsm4(ah[mi][0], ah[mi][1], ah[mi][2], ah[mi][3], AHu + rbase + aoff);
                ldsm4(al[mi][0], al[mi][1], al[mi][2], al[mi][3], ALu + rbase + aoff);
            }
#pragma unroll
            for (int no = 0; no < 2; no++) {
                uint32_t nbase = (uint32_t)((nw * 32 + no * 16) * 40) * 2u;
                ldsm4(bh[2 * no][0], bh[2 * no][1], bh[2 * no + 1][0], bh[2 * no + 1][1],
                      BHu + nbase + boff);
                ldsm4(bl[2 * no][0], bl[2 * no][1], bl[2 * no + 1][0], bl[2 * no + 1][1],
                      BLu + nbase + boff);
            }
#pragma unroll
            for (int mi = 0; mi < 2; mi++)
#pragma unroll
                for (int ni = 0; ni < 4; ni++) {
                    MMA_BF16(acc[mi][ni], al[mi][0], al[mi][1], al[mi][2], al[mi][3],
                             bh[ni][0], bh[ni][1]);
                    MMA_BF16(acc[mi][ni], ah[mi][0], ah[mi][1], ah[mi][2], ah[mi][3],
                             bl[ni][0], bl[ni][1]);
                    MMA_BF16(acc[mi][ni], ah[mi][0], ah[mi][1], ah[mi][2], ah[mi][3],
                             bh[ni][0], bh[ni][1]);
                }
        }
        __syncthreads();
    }
#undef K2_COPY

    // fp32 partial store
    const int ar = lane >> 2;
    const int qq = lane & 3;
    float* WP = g_WPp[ksp] + (size_t)b * 512 * NCS;
#pragma unroll
    for (int mi = 0; mi < 2; mi++)
#pragma unroll
        for (int rh = 0; rh < 2; rh++) {
            int row = which * 256 + o0 + mw * 32 + mi * 16 + ar + rh * 8;
#pragma unroll
            for (int ni = 0; ni < 4; ni++) {
                int col = nw * 32 + ni * 8 + 2 * qq;
                float2 o;
                o.x = acc[mi][ni][rh * 2 + 0];
                o.y = acc[mi][ni][rh * 2 + 1];
                *reinterpret_cast<float2*>(WP + (size_t)row * NCS + col) = o;
            }
        }
}

// ---------------- K2r: reduce 4 partials -> split bf16 ------------------------
__global__ void __launch_bounds__(256) k2r()
{
    const size_t idx = ((size_t)blockIdx.x * 256 + threadIdx.x) * 4;   // over NB*512*64
    const size_t STRIDE = (size_t)NB * 512 * NCS;
    float4 s = *reinterpret_cast<const float4*>(&g_WPp[0][0] + idx);
    float4 t1 = *reinterpret_cast<const float4*>(&g_WPp[0][0] + STRIDE + idx);
    float4 t2 = *reinterpret_cast<const float4*>(&g_WPp[0][0] + 2 * STRIDE + idx);
    float4 t3 = *reinterpret_cast<const float4*>(&g_WPp[0][0] + 3 * STRIDE + idx);
    s.x += t1.x + (t2.x + t3.x);
    s.y += t1.y + (t2.y + t3.y);
    s.z += t1.z + (t2.z + t3.z);
    s.w += t1.w + (t2.w + t3.w);
    __nv_bfloat16 h0, l0, h1, l1, h2, l2, h3, l3;
    bf16_split(s.x, h0, l0); bf16_split(s.y, h1, l1);
    bf16_split(s.z, h2, l2); bf16_split(s.w, h3, l3);
    *reinterpret_cast<uint2*>(&g_WPh[idx]) = make_uint2(pk2(h0, h1), pk2(h2, h3));
    *reinterpret_cast<uint2*>(&g_WPl[idx]) = make_uint2(pk2(l0, l1), pk2(l2, l3));
}

// ---------------- K3: quarter tile C[64px, 128f] = A[px,64c] @ B[f,64c]^T -----
__global__ void __launch_bounds__(128) k3_mma(const float* __restrict__ b4)
{
    extern __shared__ __nv_bfloat16 smb[];
    const int AH = 0, AL = 4608, BH = 9216, BL = 18432;
    const uint32_t smb_u = smem_u32(smb);
    const int tid = threadIdx.x;
    const int lane = tid & 31;
    const int wid = tid >> 5;
    const int mw = wid & 1;
    const int nwf = wid >> 1;
    const int p0 = blockIdx.x * 64;
    const int by = blockIdx.y;
    const int which = by >> 1;
    const int nt = by & 1;
    const int b = blockIdx.z;

    const int lrA = lane & 15;
    const int lkA = (lane >> 4) << 3;
    const int lnB = (lane & 7) + ((lane >> 4) << 3);
    const int lkB = ((lane >> 3) & 1) << 3;

    {
        const __nv_bfloat16* srch = g_WPh + ((size_t)b * 512 + which * 256 + nt * 128) * NCS;
        const __nv_bfloat16* srcl = g_WPl + ((size_t)b * 512 + which * 256 + nt * 128) * NCS;
        for (int i = tid; i < 1024; i += 128) {
            int row = i >> 3, q = i & 7;
            uint32_t dh = smb_u + (uint32_t)(BH + row * 72 + q * 8) * 2u;
            uint32_t dl = smb_u + (uint32_t)(BL + row * 72 + q * 8) * 2u;
            size_t so = (size_t)row * NCS + q * 8;
            asm volatile("cp.async.ca.shared.global [%0], [%1], 16;" :: "r"(dh), "l"(srch + so));
            asm volatile("cp.async.ca.shared.global [%0], [%1], 16;" :: "r"(dl), "l"(srcl + so));
        }
        asm volatile("cp.async.commit_group;");
    }
    if (which == 0) {
        const float* th = g_theta + (size_t)b * NCS * NHW;
        for (int i = tid; i < 1024; i += 128) {
            int c = (i & 15) + ((i >> 8) << 4);
            int pq = (i >> 4) & 15;
            float4 v = *reinterpret_cast<const float4*>(th + (size_t)c * NHW + p0 + pq * 4);
#pragma unroll
            for (int j = 0; j < 4; j++) {
                __nv_bfloat16 h, l;
                bf16_split(f4get(v, j), h, l);
                smb[AH + (pq * 4 + j) * 72 + c] = h;
                smb[AL + (pq * 4 + j) * 72 + c] = l;
            }
        }
    } else {
        const float* ph = g_phi + (size_t)b * NCS * NHW;
        for (int i = tid; i < 1024; i += 128) {
            int p = i >> 4, cq = i & 15;
            float4 v = *reinterpret_cast<const float4*>(ph + (size_t)(p0 + p) * NCS + cq * 4);
            __nv_bfloat16 h0, l0, h1, l1, h2, l2, h3, l3;
            bf16_split(v.x, h0, l0); bf16_split(v.y, h1, l1);
            bf16_split(v.z, h2, l2); bf16_split(v.w, h3, l3);
            *reinterpret_cast<uint2*>(&smb[AH + p * 72 + cq * 4]) =
                make_uint2(pk2(h0, h1), pk2(h2, h3));
            *reinterpret_cast<uint2*>(&smb[AL + p * 72 + cq * 4]) =
                make_uint2(pk2(l0, l1), pk2(l2, l3));
        }
    }
    asm volatile("cp.async.wait_group 0;");
    __syncthreads();

    float acc[2][8][4];
#pragma unroll
    for (int mi = 0; mi < 2; mi++)
#pragma unroll
        for (int ni = 0; ni < 8; ni++)
#pragma unroll
            for (int c = 0; c < 4; c++) acc[mi][ni][c] = 0.f;

#pragma unroll
    for (int ks = 0; ks < 4; ks++) {
        uint32_t ah[2][4], al[2][4], bh[8][2], bl[8][2];
        const uint32_t aoff = (uint32_t)(lrA * 72 + ks * 16 + lkA) * 2u;
        const uint32_t boff = (uint32_t)(lnB * 72 + ks * 16 + lkB) * 2u;
#pragma unroll
        for (int mi = 0; mi < 2; mi++) {
            uint32_t rb = (uint32_t)((mw * 32 + mi * 16) * 72) * 2u;
            ldsm4(ah[mi][0], ah[mi][1], ah[mi][2], ah[mi][3],
                  smb_u + (uint32_t)(AH * 2) + rb + aoff);
            ldsm4(al[mi][0], al[mi][1], al[mi][2], al[mi][3],
                  smb_u + (uint32_t)(AL * 2) + rb + aoff);
        }
#pragma unroll
        for (int no = 0; no < 4; no++) {
            uint32_t nb = (uint32_t)((nwf * 64 + no * 16) * 72) * 2u;
            ldsm4(bh[2 * no][0], bh[2 * no][1], bh[2 * no + 1][0], bh[2 * no + 1][1],
                  smb_u + (uint32_t)(BH * 2) + nb + boff);
            ldsm4(bl[2 * no][0], bl[2 * no][1], bl[2 * no + 1][0], bl[2 * no + 1][1],
                  smb_u + (uint32_t)(BL * 2) + nb + boff);
        }
#pragma unroll
        for (int ni = 0; ni < 8; ni++)
#pragma unroll
            for (int mi = 0; mi < 2; mi++) {
                MMA_BF16(acc[mi][ni], al[mi][0], al[mi][1], al[mi][2], al[mi][3],
                         bh[ni][0], bh[ni][1]);
                MMA_BF16(acc[mi][ni], ah[mi][0], ah[mi][1], ah[mi][2], ah[mi][3],
                         bl[ni][0], bl[ni][1]);
                MMA_BF16(acc[mi][ni], ah[mi][0], ah[mi][1], ah[mi][2], ah[mi][3],
                         bh[ni][0], bh[ni][1]);
            }
    }

    const int ar = lane >> 2;
    const int qq = lane & 3;
#pragma unroll
    for (int ni = 0; ni < 8; ni++) {
        int o = nt * 128 + nwf * 64 + ni * 8 + 2 * qq;
        float2 bb = *reinterpret_cast<const float2*>(b4 + o);
        int f0 = which * 256 + o;
#pragma unroll
        for (int mi = 0; mi < 2; mi++)
#pragma unroll
            for (int rh = 0; rh < 2; rh++) {
                int px = p0 + mw * 32 + mi * 16 + ar + rh * 8;
                float v0 = fmaxf(acc[mi][ni][rh * 2 + 0] + bb.x, 0.f);
                float v1 = fmaxf(acc[mi][ni][rh * 2 + 1] + bb.y, 0.f);
                __nv_bfloat16 h0, l0, h1, l1;
                bf16_split(v0, h0, l0);
                bf16_split(v1, h1, l1);
                size_t base = (size_t)(b * NHW + px) * KP + f0;
                *reinterpret_cast<uint32_t*>(&g_yh[base]) = pk2(h0, h1);
                *reinterpret_cast<uint32_t*>(&g_yl[base]) = pk2(l0, l1);
            }
    }
}

// ---------------- K4: quarter-tile split-bf16 GEMM + partial-logit epilogue ---
__global__ void __launch_bounds__(128, 3) k4_mma(const float* __restrict__ w6)
{
    extern __shared__ __nv_bfloat16 smb[];
    const int AH = 0, AL = 10240, BH = 20480, BL = 25600;
    const uint32_t smb_u = smem_u32(smb);
    const int tid = threadIdx.x;
    const int lane = tid & 31;
    const int wid = tid >> 5;
    const int mw = wid & 1;
    const int nw = wid >> 1;
    const int p0 = blockIdx.x * 64;
    const int mt = blockIdx.y;
    const int b = blockIdx.z;
    const size_t pixbase = (size_t)(b * NHW + p0);
    const size_t arowbase = (size_t)(mt * 128) * KP;

    const int lrA = lane & 15;
    const int lkA = (lane >> 4) << 3;
    const int lnB = (lane & 7) + ((lane >> 4) << 3);
    const int lkB = ((lane >> 3) & 1) << 3;

    float acc[4][4][4];
#pragma unroll
    for (int mi = 0; mi < 4; mi++)
#pragma unroll
        for (int ni = 0; ni < 4; ni++)
#pragma unroll
            for (int c = 0; c < 4; c++) acc[mi][ni][c] = 0.f;

#define COPY_CHUNK(ch, buf) do {                                                     \
    for (int i = tid; i < 512; i += 128) {                                           \
        int row = i >> 2, q = i & 3;                                                 \
        uint32_t dh = smb_u + (uint32_t)(AH + (buf) * 5120 + row * 40 + q * 8) * 2u; \
        uint32_t dl = smb_u + (uint32_t)(AL + (buf) * 5120 + row * 40 + q * 8) * 2u; \
        size_t so = arowbase + (size_t)row * KP + (ch) * 32 + q * 8;                 \
        asm volatile("cp.async.ca.shared.global [%0], [%1], 16;" :: "r"(dh), "l"(g_w5h + so)); \
        asm volatile("cp.async.ca.shared.global [%0], [%1], 16;" :: "r"(dl), "l"(g_w5l + so)); \
    }                                                                                \
    for (int i = tid; i < 256; i += 128) {                                           \
        int row = i >> 2, q = i & 3;                                                 \
        uint32_t dh = smb_u + (uint32_t)(BH + (buf) * 2560 + row * 40 + q * 8) * 2u; \
        uint32_t dl = smb_u + (uint32_t)(BL + (buf) * 2560 + row * 40 + q * 8) * 2u; \
        size_t so = (pixbase + row) * KP + (ch) * 32 + q * 8;                        \
        asm volatile("cp.async.ca.shared.global [%0], [%1], 16;" :: "r"(dh), "l"(g_yh + so)); \
        asm volatile("cp.async.ca.shared.global [%0], [%1], 16;" :: "r"(dl), "l"(g_yl + so)); \
    }                                                                                \
    asm volatile("cp.async.commit_group;");                                          \
} while (0)

    COPY_CHUNK(0, 0);
    for (int ch = 0; ch < NCHUNK; ch++) {
        if (ch < NCHUNK - 1) {
            COPY_CHUNK(ch + 1, (ch + 1) & 1);
            asm volatile("cp.async.wait_group 1;");
        } else {
            asm volatile("cp.async.wait_group 0;");
        }
        __syncthreads();
        const int buf = ch & 1;
        const uint32_t AHu = smb_u + (uint32_t)(AH + buf * 5120) * 2u;
        const uint32_t ALu = smb_u + (uint32_t)(AL + buf * 5120) * 2u;
        const uint32_t BHu = smb_u + (uint32_t)(BH + buf * 2560) * 2u;
        const uint32_t BLu = smb_u + (uint32_t)(BL + buf * 2560) * 2u;
#pragma unroll
        for (int ks = 0; ks < 2; ks++) {
            uint32_t ah[4][4], al[4][4], bh[4][2], bl[4][2];
            const uint32_t aoff = (uint32_t)(lrA * 40 + ks * 16 + lkA) * 2u;
            const uint32_t boff = (uint32_t)(lnB * 40 + ks * 16 + lkB) * 2u;
#pragma unroll
            for (int mi = 0; mi < 4; mi++) {
                uint32_t rbase = (uint32_t)((mw * 64 + mi * 16) * 40) * 2u;
                ldsm4(ah[mi][0], ah[mi][1], ah[mi][2], ah[mi][3], AHu + rbase + aoff);
                ldsm4(al[mi][0], al[mi][1], al[mi][2], al[mi][3], ALu + rbase + aoff);
            }
#pragma unroll
            for (int no = 0; no < 2; no++) {
                uint32_t nbase = (uint32_t)((nw * 32 + no * 16) * 40) * 2u;
                ldsm4(bh[2 * no][0], bh[2 * no][1], bh[2 * no + 1][0], bh[2 * no + 1][1],
                      BHu + nbase + boff);
                ldsm4(bl[2 * no][0], bl[2 * no][1], bl[2 * no + 1][0], bl[2 * no + 1][1],
                      BLu + nbase + boff);
            }
#pragma unroll
            for (int mi = 0; mi < 4; mi++)
#pragma unroll
                for (int ni = 0; ni < 4; ni++) {
                    MMA_BF16(acc[mi][ni], al[mi][0], al[mi][1], al[mi][2], al[mi][3],
                             bh[ni][0], bh[ni][1]);
                    MMA_BF16(acc[mi][ni], ah[mi][0], ah[mi][1], ah[mi][2], ah[mi][3],
                             bl[ni][0], bl[ni][1]);
                    MMA_BF16(acc[mi][ni], ah[mi][0], ah[mi][1], ah[mi][2], ah[mi][3],
                             bh[ni][0], bh[ni][1]);
                }
        }
        __syncthreads();
    }
#undef COPY_CHUNK

    float shv[8], wkv[8];
#pragma unroll
    for (int mi = 0; mi < 4; mi++)
#pragma unroll
        for (int rh = 0; rh < 2; rh++) {
            int m = mt * 128 + mw * 64 + mi * 16 + (lane >> 2) + rh * 8;
            shv[mi * 2 + rh] = g_sh5[m];
            wkv[mi * 2 + rh] = w6[m];
        }

    float* red = reinterpret_cast<float*>(smb);     // [64][17]
    const int slice = mw * 8 + (lane >> 2);
#pragma unroll
    for (int ni = 0; ni < 4; ni++)
#pragma unroll
        for (int j = 0; j < 2; j++) {
            float s = 0.f;
#pragma unroll
            for (int mi = 0; mi < 4; mi++)
#pragma unroll
                for (int rh = 0; rh < 2; rh++) {
                    float z = fmaxf(acc[mi][ni][rh * 2 + j] + shv[mi * 2 + rh], 0.f);
                    s = fmaf(z, wkv[mi * 2 + rh], s);
                }
            int col = nw * 32 + ni * 8 + 2 * (lane & 3) + j;
            red[col * 17 + slice] = s;
        }
    __syncthreads();
    if (tid < 64) {
        float t = 0.f;
#pragma unroll
        for (int r = 0; r < 16; r++) t += red[tid * 17 + r];
        g_part[mt][b * NHW + p0 + tid] = t;
    }
}

// ---------------- K5: a = sigmoid(part0+part1+b6); out = x * a ----------------
__global__ void __launch_bounds__(256) k5_scale(const float* __restrict__ x,
                                                const float* __restrict__ b6,
                                                float* __restrict__ out)
{
    int idx = blockIdx.x * 256 + threadIdx.x;
    float4 xv = reinterpret_cast<const float4*>(x)[idx];
    int pix4 = idx & 255;
    int b = idx >> 16;
    float4 t0 = reinterpret_cast<const float4*>(g_part[0])[b * 256 + pix4];
    float4 t1 = reinterpret_cast<const float4*>(g_part[1])[b * 256 + pix4];
    float bb = b6[0];
    float4 av;
    av.x = 1.f / (1.f + expf(-(t0.x + t1.x + bb)));
    av.y = 1.f / (1.f + expf(-(t0.y + t1.y + bb)));
    av.z = 1.f / (1.f + expf(-(t0.z + t1.z + bb)));
    av.w = 1.f / (1.f + expf(-(t0.w + t1.w + bb)));
    float4 o;
    o.x = xv.x * av.x; o.y = xv.y * av.y; o.z = xv.z * av.z; o.w = xv.w * av.w;
    reinterpret_cast<float4*>(out)[idx] = o;
}

// ---------------- launch ------------------------------------------------------
extern "C" void kernel_launch(void* const* d_in, const int* in_sizes, int n_in,
                              void* d_out, int out_size)
{
    const float* x   = (const float*)d_in[0];
    const float* w1  = (const float*)d_in[1];
    const float* b1  = (const float*)d_in[2];
    const float* g1  = (const float*)d_in[3];
    const float* bt1 = (const float*)d_in[4];
    const float* m1  = (const float*)d_in[5];
    const float* v1  = (const float*)d_in[6];
    const float* w2  = (const float*)d_in[7];
    const float* b2  = (const float*)d_in[8];
    const float* g2  = (const float*)d_in[9];
    const float* bt2 = (const float*)d_in[10];
    const float* m2  = (const float*)d_in[11];
    const float* v2  = (const float*)d_in[12];
    const float* w3  = (const float*)d_in[13];
    const float* b3  = (const float*)d_in[14];
    const float* g3  = (const float*)d_in[15];
    const float* bt3 = (const float*)d_in[16];
    const float* m3  = (const float*)d_in[17];
    const float* v3  = (const float*)d_in[18];
    const float* w4  = (const float*)d_in[19];
    const float* b4  = (const float*)d_in[20];
    const float* w5  = (const float*)d_in[21];
    const float* b5  = (const float*)d_in[22];
    const float* g5  = (const float*)d_in[23];
    const float* bt5 = (const float*)d_in[24];
    const float* m5  = (const float*)d_in[25];
    const float* v5  = (const float*)d_in[26];
    const float* w6  = (const float*)d_in[27];
    const float* b6  = (const float*)d_in[28];

    cudaFuncSetAttribute(k1_mma, cudaFuncAttributeMaxDynamicSharedMemorySize, 102400);
    cudaFuncSetAttribute(k2_mma, cudaFuncAttributeMaxDynamicSharedMemorySize, 40960);
    cudaFuncSetAttribute(k3_mma, cudaFuncAttributeMaxDynamicSharedMemorySize, 55296);
    cudaFuncSetAttribute(k4_mma, cudaFuncAttributeMaxDynamicSharedMemorySize, 61440);

    k0_prep<<<NC5 + 1 + NB + 192 + 256, 256>>>(w5, g5, v5, b5, bt5, m5, w4,
                                               w1, b1, g1, bt1, m1, v1,
                                               w2, b2, g2, bt2, m2, v2,
                                               w3, b3, g3, bt3, m3, v3);
    k1_mma<<<dim3(8, NB), 384, 102400>>>(x);
    k2t<<<dim3(16, NB), 256>>>();
    k2_mma<<<dim3(4, 2, NB * 4), 128, 40960>>>();
    k2r<<<1024, 256>>>();
    k3_mma<<<dim3(16, 4, NB), 128, 55296>>>(b4);
    k4_mma<<<dim3(16, 2, NB), 128, 61440>>>(w6);
    k5_scale<<<(NB * NINP * NHW / 4) / 256, 256>>>(x, b6, (float*)d_out);
}